// round 9
// baseline (speedup 1.0000x reference)
#include <cuda_runtime.h>
#include <cuda_bf16.h>
#include <math.h>
#include <stdint.h>

#define N_ELEM 131072
#define C_DIM  512
#define G_DIM  4096
#define NOUT   1024     // Wf cols || Wg cols

// ---------------- scratch (device globals; no allocation allowed) ----------------
__device__ __nv_bfloat16 g_whi[(size_t)NOUT * C_DIM];     // 1 MB, K-major [n][k]
__device__ __nv_bfloat16 g_wlo[(size_t)NOUT * C_DIM];     // 1 MB
__device__ float g_eg[(size_t)N_ELEM * C_DIM];            // 256 MB
__device__ float g_denom[G_DIM * C_DIM];                  // 8 MB
__device__ float g_y[G_DIM * C_DIM];                      // 8 MB
__device__ float g_yh[G_DIM * C_DIM];                     // 8 MB

#define MMA16816(d, a0, a1, a2, a3, b0, b1) \
    asm volatile("mma.sync.aligned.m16n8k16.row.col.f32.bf16.bf16.f32 " \
                 "{%0,%1,%2,%3}, {%4,%5,%6,%7}, {%8,%9}, {%0,%1,%2,%3};" \
                 : "+f"((d)[0]), "+f"((d)[1]), "+f"((d)[2]), "+f"((d)[3]) \
                 : "r"(a0), "r"(a1), "r"(a2), "r"(a3), "r"(b0), "r"(b1))

#define LDSM_X4(R0, R1, R2, R3, addr) \
    asm volatile("ldmatrix.sync.aligned.m8n8.x4.shared.b16 {%0,%1,%2,%3}, [%4];" \
                 : "=r"(R0), "=r"(R1), "=r"(R2), "=r"(R3) : "r"(addr))

__device__ __forceinline__ uint32_t smem_u32(const void* p) {
    uint32_t a;
    asm("{ .reg .u64 t; cvta.to.shared.u64 t, %1; cvt.u32.u64 %0, t; }" : "=r"(a) : "l"(p));
    return a;
}
__device__ __forceinline__ void cp16(uint32_t saddr, const void* g) {
    asm volatile("cp.async.cg.shared.global [%0], [%1], 16;" :: "r"(saddr), "l"(g));
}

// ---------------- zero accumulators ----------------
__global__ void zero_kernel() {
    int i = blockIdx.x * blockDim.x + threadIdx.x;   // G*C/4
    float4 z = make_float4(0.f, 0.f, 0.f, 0.f);
    ((float4*)g_denom)[i] = z;
    ((float4*)g_y)[i] = z;
}

// ---------------- build Whi/Wlo [n=1024][k=512] K-major bf16 ----------------
__global__ void build_w_kernel(const float* __restrict__ Wf,
                               const float* __restrict__ Wg) {
    int i = blockIdx.x * blockDim.x + threadIdx.x;   // NOUT*C_DIM
    int n = i >> 9;
    int k = i & 511;
    const float* W = (n < 512) ? Wf : Wg;
    float w = W[(size_t)k * C_DIM + (n & 511)];
    __nv_bfloat16 hi = __float2bfloat16(w);
    g_whi[i] = hi;
    g_wlo[i] = __float2bfloat16(w - __bfloat162float(hi));
}

// ---------------- mma.sync bf16-split GEMM halves ------------------------------
// R8 mainloop with fragment loads converted to ldmatrix.x4 (80B pitch verified
// conflict-free; R3's ldmatrix failure was a writer pitch mismatch, fixed here
// by using the same SPITCH on both sides).
// IS_G=true : eg = exp(x Wg + bg) -> store g_eg, atomics into g_denom.
// IS_G=false: fx = x Wf + bf in regs -> read eg/denom, atomicAdd y += fx*eg/den.
#define SPITCH 40
#define PITCHB 80                    // bytes per row
#define TILE_E (128 * SPITCH)        // bf16 elems per tile
#define TILE_B (TILE_E * 2)          // 10240 bytes per tile
#define STG_E  (4 * TILE_E)          // elems per stage (AHI, ALO, BHI, BLO)
#define STG_B  (4 * TILE_B)

template <bool IS_G>
__global__ __launch_bounds__(256, 2)
void gemm_half(const float* __restrict__ x, const int* __restrict__ ix,
               const float* __restrict__ bias) {
    extern __shared__ __nv_bfloat16 sm[];

    const int tid  = threadIdx.x;
    const int l    = tid & 31;
    const int warp = tid >> 5;
    const int bx   = blockIdx.x;          // 0..3 -> 128-col stripe of this half
    const int row0 = blockIdx.y * 128;
    const int n0g  = (IS_G ? 512 : 0) + bx * 128;

    const int wm = warp >> 2;             // 0..1
    const int wn = warp & 3;              // 0..3
    const int m_base = wm * 64;
    const int n_base = wn * 32;
    const int gid = l >> 2, tig = l & 3;

    const uint32_t sbase = smem_u32(sm);
    const uint32_t lane_off = (uint32_t)((l & 15) * PITCHB + (l >> 4) * 16);

    float acc[4][4][4];
#pragma unroll
    for (int t = 0; t < 4; t++)
#pragma unroll
        for (int n = 0; n < 4; n++)
#pragma unroll
            for (int r = 0; r < 4; r++) acc[t][n][r] = 0.f;

    float4 stg[4];

#define LOAD_A(CH) do {                                                       \
        const int kc_ = (CH) * 32;                                            \
        _Pragma("unroll")                                                     \
        for (int i_ = 0; i_ < 4; i_++) {                                      \
            int u_ = tid + i_ * 256;                                          \
            int r_ = u_ >> 3, s_ = u_ & 7;                                    \
            stg[i_] = *(const float4*)(x + (size_t)(row0 + r_) * C_DIM + kc_ + s_ * 4); \
        }                                                                     \
    } while (0)

#define STORE_A(BUF) do {                                                     \
        __nv_bfloat16* ahi_ = sm + (BUF) * STG_E;                             \
        __nv_bfloat16* alo_ = ahi_ + TILE_E;                                  \
        _Pragma("unroll")                                                     \
        for (int i_ = 0; i_ < 4; i_++) {                                      \
            int u_ = tid + i_ * 256;                                          \
            int r_ = u_ >> 3, s_ = u_ & 7;                                    \
            float4 v_ = stg[i_];                                              \
            __nv_bfloat162 h01_, h23_, l01_, l23_;                            \
            h01_.x = __float2bfloat16(v_.x); h01_.y = __float2bfloat16(v_.y); \
            h23_.x = __float2bfloat16(v_.z); h23_.y = __float2bfloat16(v_.w); \
            l01_.x = __float2bfloat16(v_.x - __bfloat162float(h01_.x));       \
            l01_.y = __float2bfloat16(v_.y - __bfloat162float(h01_.y));       \
            l23_.x = __float2bfloat16(v_.z - __bfloat162float(h23_.x));       \
            l23_.y = __float2bfloat16(v_.w - __bfloat162float(h23_.y));       \
            uint2 H_, L_;                                                     \
            H_.x = *(uint32_t*)&h01_; H_.y = *(uint32_t*)&h23_;               \
            L_.x = *(uint32_t*)&l01_; L_.y = *(uint32_t*)&l23_;               \
            *(uint2*)(ahi_ + r_ * SPITCH + s_ * 4) = H_;                      \
            *(uint2*)(alo_ + r_ * SPITCH + s_ * 4) = L_;                      \
        }                                                                     \
    } while (0)

#define LOAD_B(BUF, CH) do {                                                  \
        const int kc_ = (CH) * 32;                                            \
        uint32_t bhi_ = sbase + (BUF) * STG_B + 2 * TILE_B;                   \
        uint32_t blo_ = bhi_ + TILE_B;                                        \
        _Pragma("unroll")                                                     \
        for (int i_ = 0; i_ < 2; i_++) {                                      \
            int u_ = tid + i_ * 256;                                          \
            int nr_ = u_ >> 2, ch_ = u_ & 3;                                  \
            size_t go_ = (size_t)(n0g + nr_) * C_DIM + kc_ + ch_ * 8;         \
            uint32_t so_ = nr_ * PITCHB + ch_ * 16;                           \
            cp16(bhi_ + so_, g_whi + go_);                                    \
            cp16(blo_ + so_, g_wlo + go_);                                    \
        }                                                                     \
        asm volatile("cp.async.commit_group;" ::: "memory");                  \
    } while (0)

    LOAD_B(0, 0);
    LOAD_A(0);
    STORE_A(0);
    asm volatile("cp.async.wait_group 0;" ::: "memory");
    __syncthreads();

    for (int it = 0; it < 16; it++) {
        const int cur = it & 1;
        if (it + 1 < 16) {
            LOAD_B(cur ^ 1, it + 1);
            LOAD_A(it + 1);
        }

        const uint32_t AhiB = sbase + cur * STG_B;
        const uint32_t AloB = AhiB + TILE_B;
        const uint32_t BhiB = AhiB + 2 * TILE_B;
        const uint32_t BloB = AhiB + 3 * TILE_B;

#pragma unroll
        for (int s = 0; s < 2; s++) {
            const uint32_t ks = lane_off + s * 32;
            // B fragments: 2 n16-pairs x {hi,lo}, ldmatrix.x4 each
            uint32_t bH[4][2], bL[4][2];
#pragma unroll
            for (int p = 0; p < 2; p++) {
                const uint32_t boff = (n_base + p * 16) * PITCHB + ks;
                LDSM_X4(bH[2*p][0], bH[2*p+1][0], bH[2*p][1], bH[2*p+1][1],
                        BhiB + boff);
                LDSM_X4(bL[2*p][0], bL[2*p+1][0], bL[2*p][1], bL[2*p+1][1],
                        BloB + boff);
            }
#pragma unroll
            for (int t = 0; t < 4; t++) {
                const uint32_t aoff = (m_base + t * 16) * PITCHB + ks;
                uint32_t aH[4], aL[4];
                LDSM_X4(aH[0], aH[1], aH[2], aH[3], AhiB + aoff);
                LDSM_X4(aL[0], aL[1], aL[2], aL[3], AloB + aoff);
#pragma unroll
                for (int nt = 0; nt < 4; nt++) {
                    MMA16816(acc[t][nt], aH[0], aH[1], aH[2], aH[3],
                             bH[nt][0], bH[nt][1]);
                    MMA16816(acc[t][nt], aH[0], aH[1], aH[2], aH[3],
                             bL[nt][0], bL[nt][1]);
                    MMA16816(acc[t][nt], aL[0], aL[1], aL[2], aL[3],
                             bH[nt][0], bH[nt][1]);
                }
            }
        }

        if (it + 1 < 16) {
            STORE_A(cur ^ 1);
            asm volatile("cp.async.wait_group 0;" ::: "memory");
        }
        __syncthreads();
    }
#undef LOAD_A
#undef STORE_A
#undef LOAD_B

    // ---- epilogue ----
#pragma unroll
    for (int t = 0; t < 4; t++) {
#pragma unroll
        for (int h = 0; h < 2; h++) {
            const int m = row0 + m_base + t * 16 + gid + h * 8;
            const int grp = ix[m];
#pragma unroll
            for (int nt = 0; nt < 4; nt++) {
                const int cg = n0g + n_base + nt * 8 + 2 * tig;
                const int cw = cg & 511;
                float v0 = acc[t][nt][2 * h]     + bias[cw];
                float v1 = acc[t][nt][2 * h + 1] + bias[cw + 1];
                if (IS_G) {
                    v0 = expf(v0);
                    v1 = expf(v1);
                    *(float2*)&g_eg[(size_t)m * C_DIM + cw] = make_float2(v0, v1);
                    float* dp = &g_denom[(size_t)grp * C_DIM + cw];
                    atomicAdd(dp,     v0);
                    atomicAdd(dp + 1, v1);
                } else {
                    float2 e = *(const float2*)&g_eg[(size_t)m * C_DIM + cw];
                    float2 d = *(const float2*)&g_denom[(size_t)grp * C_DIM + cw];
                    float* yp = &g_y[(size_t)grp * C_DIM + cw];
                    atomicAdd(yp,     v0 * (e.x / d.x));
                    atomicAdd(yp + 1, v1 * (e.y / d.y));
                }
            }
        }
    }
}

// ---------------- yh = y @ Wh + bh (fp32 SIMT, small) ----------------
__global__ __launch_bounds__(256, 2)
void gemm_h_kernel(const float* __restrict__ Wh, const float* __restrict__ bh)
{
    constexpr int BM = 128, BN = 128, BK = 16;
    __shared__ float As[BK][BM];
    __shared__ float Bs[BK][BN];

    const int tid  = threadIdx.x;
    const int col0 = blockIdx.x * BN;
    const int row0 = blockIdx.y * BM;
    const int ty = tid >> 4, tx = tid & 15;
    const int trow = ty * 8, tcol = tx * 8;

    float acc[8][8];
#pragma unroll
    for (int i = 0; i < 8; i++)
#pragma unroll
        for (int j = 0; j < 8; j++) acc[i][j] = 0.f;

    for (int k0 = 0; k0 < C_DIM; k0 += BK) {
#pragma unroll
        for (int s = 0; s < 2; s++) {
            int ll = tid + s * 256;
            int ar  = ll >> 2;
            int akq = (ll & 3) * 4;
            float4 av = *(const float4*)&g_y[(size_t)(row0 + ar) * C_DIM + k0 + akq];
            As[akq + 0][ar] = av.x;
            As[akq + 1][ar] = av.y;
            As[akq + 2][ar] = av.z;
            As[akq + 3][ar] = av.w;
            int bk  = ll >> 5;
            int bcq = (ll & 31) * 4;
            float4 bv = *(const float4*)&Wh[(size_t)(k0 + bk) * C_DIM + col0 + bcq];
            *(float4*)&Bs[bk][bcq] = bv;
        }
        __syncthreads();
#pragma unroll
        for (int k = 0; k < BK; k++) {
            float a[8], b[8];
#pragma unroll
            for (int i = 0; i < 8; i++) a[i] = As[k][trow + i];
#pragma unroll
            for (int j = 0; j < 8; j++) b[j] = Bs[k][tcol + j];
#pragma unroll
            for (int i = 0; i < 8; i++)
#pragma unroll
                for (int j = 0; j < 8; j++)
                    acc[i][j] = fmaf(a[i], b[j], acc[i][j]);
        }
        __syncthreads();
    }

    float bv[8];
#pragma unroll
    for (int j = 0; j < 8; j++) bv[j] = bh[col0 + tcol + j];
#pragma unroll
    for (int i = 0; i < 8; i++) {
        size_t off = (size_t)(row0 + trow + i) * C_DIM + col0 + tcol;
        *(float4*)&g_yh[off]     = make_float4(acc[i][0] + bv[0], acc[i][1] + bv[1],
                                               acc[i][2] + bv[2], acc[i][3] + bv[3]);
        *(float4*)&g_yh[off + 4] = make_float4(acc[i][4] + bv[4], acc[i][5] + bv[5],
                                               acc[i][6] + bv[6], acc[i][7] + bv[7]);
    }
}

// ---------------- out[n] = yh[ix[n]] ----------------
__global__ void gather_kernel(const int* __restrict__ ix, float* __restrict__ out) {
    size_t idx = (size_t)blockIdx.x * blockDim.x + threadIdx.x;  // N*C/4
    int n  = (int)(idx >> 7);
    int cq = (int)(idx & 127) << 2;
    int g  = ix[n];
    *(float4*)&out[((size_t)n << 9) + cq] = *(const float4*)&g_yh[((size_t)g << 9) + cq];
}

extern "C" void kernel_launch(void* const* d_in, const int* in_sizes, int n_in,
                              void* d_out, int out_size) {
    const float* x  = (const float*)d_in[0];
    const int*   ix = (const int*)d_in[1];
    const float* Wf = (const float*)d_in[2];
    const float* bf = (const float*)d_in[3];
    const float* Wg = (const float*)d_in[4];
    const float* bg = (const float*)d_in[5];
    const float* Wh = (const float*)d_in[6];
    const float* bh = (const float*)d_in[7];
    float* out = (float*)d_out;

    const int SMEM = 2 * STG_B;   // 81920 bytes
    cudaFuncSetAttribute(gemm_half<true>,  cudaFuncAttributeMaxDynamicSharedMemorySize, SMEM);
    cudaFuncSetAttribute(gemm_half<false>, cudaFuncAttributeMaxDynamicSharedMemorySize, SMEM);

    zero_kernel<<<(G_DIM * C_DIM / 4) / 256, 256>>>();
    build_w_kernel<<<(NOUT * C_DIM) / 256, 256>>>(Wf, Wg);

    dim3 g1(4, N_ELEM / 128);
    gemm_half<true><<<g1, 256, SMEM>>>(x, ix, bg);    // eg + denom
    gemm_half<false><<<g1, 256, SMEM>>>(x, ix, bf);   // fx, fused aggregation

    dim3 g2(C_DIM / 128, G_DIM / 128);
    gemm_h_kernel<<<g2, 256>>>(Wh, bh);

    gather_kernel<<<(N_ELEM * (C_DIM / 4)) / 256, 256>>>(ix, out);
}

// round 10
// speedup vs baseline: 1.0480x; 1.0480x over previous
#include <cuda_runtime.h>
#include <cuda_bf16.h>
#include <math.h>
#include <stdint.h>

#define N_ELEM 131072
#define C_DIM  512
#define G_DIM  4096
#define NOUT   1024     // Wf cols || Wg cols

// ---------------- scratch (device globals; no allocation allowed) ----------------
__device__ __nv_bfloat16 g_whi[(size_t)NOUT * C_DIM];     // 1 MB, K-major [n][k]
__device__ __nv_bfloat16 g_wlo[(size_t)NOUT * C_DIM];     // 1 MB
__device__ float g_eg[(size_t)N_ELEM * C_DIM];            // 256 MB
__device__ float g_denom[G_DIM * C_DIM];                  // 8 MB
__device__ float g_y[G_DIM * C_DIM];                      // 8 MB
__device__ float g_yh[G_DIM * C_DIM];                     // 8 MB

#define MMA16816(d, a0, a1, a2, a3, b0, b1) \
    asm volatile("mma.sync.aligned.m16n8k16.row.col.f32.bf16.bf16.f32 " \
                 "{%0,%1,%2,%3}, {%4,%5,%6,%7}, {%8,%9}, {%0,%1,%2,%3};" \
                 : "+f"((d)[0]), "+f"((d)[1]), "+f"((d)[2]), "+f"((d)[3]) \
                 : "r"(a0), "r"(a1), "r"(a2), "r"(a3), "r"(b0), "r"(b1))

__device__ __forceinline__ uint32_t smem_u32(const void* p) {
    uint32_t a;
    asm("{ .reg .u64 t; cvta.to.shared.u64 t, %1; cvt.u32.u64 %0, t; }" : "=r"(a) : "l"(p));
    return a;
}
__device__ __forceinline__ void cp16(uint32_t saddr, const void* g) {
    asm volatile("cp.async.cg.shared.global [%0], [%1], 16;" :: "r"(saddr), "l"(g));
}

// ---------------- zero accumulators ----------------
__global__ void zero_kernel() {
    int i = blockIdx.x * blockDim.x + threadIdx.x;   // G*C/4
    float4 z = make_float4(0.f, 0.f, 0.f, 0.f);
    ((float4*)g_denom)[i] = z;
    ((float4*)g_y)[i] = z;
}

// ---------------- build Whi/Wlo [n=1024][k=512] K-major bf16 ----------------
__global__ void build_w_kernel(const float* __restrict__ Wf,
                               const float* __restrict__ Wg) {
    int i = blockIdx.x * blockDim.x + threadIdx.x;   // NOUT*C_DIM
    int n = i >> 9;
    int k = i & 511;
    const float* W = (n < 512) ? Wf : Wg;
    float w = W[(size_t)k * C_DIM + (n & 511)];
    __nv_bfloat16 hi = __float2bfloat16(w);
    g_whi[i] = hi;
    g_wlo[i] = __float2bfloat16(w - __bfloat162float(hi));
}

// ---------------- mma.sync bf16-split GEMM halves ------------------------------
// R8 mainloop (scalar LDS fragments, 2 CTA/SM); MMA issue order is pass-major
// within each m-tile so each accumulator's reuse distance is 4 independent
// MMAs (was 1 -> RAW stalls on the tensor pipe).
// IS_G=true : eg = exp(x Wg + bg) -> store g_eg, atomics into g_denom.
// IS_G=false: fx = x Wf + bf in regs -> read eg/denom, atomicAdd y += fx*eg/den.
#define SPITCH 40
#define TILE_E (128 * SPITCH)        // bf16 elems per tile (10240 B)
#define STG_E  (4 * TILE_E)          // elems per stage (4 tiles)

template <bool IS_G>
__global__ __launch_bounds__(256, 2)
void gemm_half(const float* __restrict__ x, const int* __restrict__ ix,
               const float* __restrict__ bias) {
    extern __shared__ __nv_bfloat16 sm[];
    // stage s: [AHI, ALO, BHI, BLO], each 128 x SPITCH

    const int tid  = threadIdx.x;
    const int l    = tid & 31;
    const int warp = tid >> 5;
    const int bx   = blockIdx.x;          // 0..3 -> 128-col stripe of this half
    const int row0 = blockIdx.y * 128;
    const int n0g  = (IS_G ? 512 : 0) + bx * 128;

    const int wm = warp >> 2;             // 0..1
    const int wn = warp & 3;              // 0..3
    const int m_base = wm * 64;
    const int n_base = wn * 32;
    const int gid = l >> 2, tig = l & 3;

    float acc[4][4][4];
#pragma unroll
    for (int t = 0; t < 4; t++)
#pragma unroll
        for (int n = 0; n < 4; n++)
#pragma unroll
            for (int r = 0; r < 4; r++) acc[t][n][r] = 0.f;

    float4 stg[4];

#define LOAD_A(CH) do {                                                       \
        const int kc_ = (CH) * 32;                                            \
        _Pragma("unroll")                                                     \
        for (int i_ = 0; i_ < 4; i_++) {                                      \
            int u_ = tid + i_ * 256;                                          \
            int r_ = u_ >> 3, s_ = u_ & 7;                                    \
            stg[i_] = *(const float4*)(x + (size_t)(row0 + r_) * C_DIM + kc_ + s_ * 4); \
        }                                                                     \
    } while (0)

#define STORE_A(BUF) do {                                                     \
        __nv_bfloat16* ahi_ = sm + (BUF) * STG_E;                             \
        __nv_bfloat16* alo_ = ahi_ + TILE_E;                                  \
        _Pragma("unroll")                                                     \
        for (int i_ = 0; i_ < 4; i_++) {                                      \
            int u_ = tid + i_ * 256;                                          \
            int r_ = u_ >> 3, s_ = u_ & 7;                                    \
            float4 v_ = stg[i_];                                              \
            __nv_bfloat162 h01_, h23_, l01_, l23_;                            \
            h01_.x = __float2bfloat16(v_.x); h01_.y = __float2bfloat16(v_.y); \
            h23_.x = __float2bfloat16(v_.z); h23_.y = __float2bfloat16(v_.w); \
            l01_.x = __float2bfloat16(v_.x - __bfloat162float(h01_.x));       \
            l01_.y = __float2bfloat16(v_.y - __bfloat162float(h01_.y));       \
            l23_.x = __float2bfloat16(v_.z - __bfloat162float(h23_.x));       \
            l23_.y = __float2bfloat16(v_.w - __bfloat162float(h23_.y));       \
            uint2 H_, L_;                                                     \
            H_.x = *(uint32_t*)&h01_; H_.y = *(uint32_t*)&h23_;               \
            L_.x = *(uint32_t*)&l01_; L_.y = *(uint32_t*)&l23_;               \
            *(uint2*)(ahi_ + r_ * SPITCH + s_ * 4) = H_;                      \
            *(uint2*)(alo_ + r_ * SPITCH + s_ * 4) = L_;                      \
        }                                                                     \
    } while (0)

#define LOAD_B(BUF, CH) do {                                                  \
        const int kc_ = (CH) * 32;                                            \
        uint32_t bhi_ = smem_u32(sm + (BUF) * STG_E + 2 * TILE_E);            \
        uint32_t blo_ = bhi_ + TILE_E * 2;                                    \
        _Pragma("unroll")                                                     \
        for (int i_ = 0; i_ < 2; i_++) {                                      \
            int u_ = tid + i_ * 256;                                          \
            int nr_ = u_ >> 2, ch_ = u_ & 3;                                  \
            size_t go_ = (size_t)(n0g + nr_) * C_DIM + kc_ + ch_ * 8;         \
            uint32_t so_ = nr_ * (SPITCH * 2) + ch_ * 16;                     \
            cp16(bhi_ + so_, g_whi + go_);                                    \
            cp16(blo_ + so_, g_wlo + go_);                                    \
        }                                                                     \
        asm volatile("cp.async.commit_group;" ::: "memory");                  \
    } while (0)

    LOAD_B(0, 0);
    LOAD_A(0);
    STORE_A(0);
    asm volatile("cp.async.wait_group 0;" ::: "memory");
    __syncthreads();

    for (int it = 0; it < 16; it++) {
        const int cur = it & 1;
        if (it + 1 < 16) {
            LOAD_B(cur ^ 1, it + 1);
            LOAD_A(it + 1);
        }

        const __nv_bfloat16* Ahi = sm + cur * STG_E;
        const __nv_bfloat16* Alo = Ahi + TILE_E;
        const __nv_bfloat16* Bhi = Ahi + 2 * TILE_E;
        const __nv_bfloat16* Blo = Ahi + 3 * TILE_E;

#pragma unroll
        for (int s = 0; s < 2; s++) {
            const int k0 = s * 16 + 2 * tig;
            uint32_t bH[4][2], bL[4][2];
#pragma unroll
            for (int nt = 0; nt < 4; nt++) {
                const int rn = n_base + nt * 8 + gid;
                bH[nt][0] = *(const uint32_t*)(Bhi + rn * SPITCH + k0);
                bH[nt][1] = *(const uint32_t*)(Bhi + rn * SPITCH + k0 + 8);
                bL[nt][0] = *(const uint32_t*)(Blo + rn * SPITCH + k0);
                bL[nt][1] = *(const uint32_t*)(Blo + rn * SPITCH + k0 + 8);
            }
#pragma unroll
            for (int t = 0; t < 4; t++) {
                const int r = m_base + t * 16 + gid;
                uint32_t aH[4], aL[4];
                aH[0] = *(const uint32_t*)(Ahi + r * SPITCH + k0);
                aH[1] = *(const uint32_t*)(Ahi + (r + 8) * SPITCH + k0);
                aH[2] = *(const uint32_t*)(Ahi + r * SPITCH + k0 + 8);
                aH[3] = *(const uint32_t*)(Ahi + (r + 8) * SPITCH + k0 + 8);
                aL[0] = *(const uint32_t*)(Alo + r * SPITCH + k0);
                aL[1] = *(const uint32_t*)(Alo + (r + 8) * SPITCH + k0);
                aL[2] = *(const uint32_t*)(Alo + r * SPITCH + k0 + 8);
                aL[3] = *(const uint32_t*)(Alo + (r + 8) * SPITCH + k0 + 8);
                // pass-major: acc[t][nt] reuse distance = 4 independent MMAs
#pragma unroll
                for (int nt = 0; nt < 4; nt++)
                    MMA16816(acc[t][nt], aH[0], aH[1], aH[2], aH[3],
                             bH[nt][0], bH[nt][1]);
#pragma unroll
                for (int nt = 0; nt < 4; nt++)
                    MMA16816(acc[t][nt], aH[0], aH[1], aH[2], aH[3],
                             bL[nt][0], bL[nt][1]);
#pragma unroll
                for (int nt = 0; nt < 4; nt++)
                    MMA16816(acc[t][nt], aL[0], aL[1], aL[2], aL[3],
                             bH[nt][0], bH[nt][1]);
            }
        }

        if (it + 1 < 16) {
            STORE_A(cur ^ 1);
            asm volatile("cp.async.wait_group 0;" ::: "memory");
        }
        __syncthreads();
    }
#undef LOAD_A
#undef STORE_A
#undef LOAD_B

    // ---- epilogue ----
#pragma unroll
    for (int t = 0; t < 4; t++) {
#pragma unroll
        for (int h = 0; h < 2; h++) {
            const int m = row0 + m_base + t * 16 + gid + h * 8;
            const int grp = ix[m];
#pragma unroll
            for (int nt = 0; nt < 4; nt++) {
                const int cg = n0g + n_base + nt * 8 + 2 * tig;
                const int cw = cg & 511;
                float v0 = acc[t][nt][2 * h]     + bias[cw];
                float v1 = acc[t][nt][2 * h + 1] + bias[cw + 1];
                if (IS_G) {
                    v0 = expf(v0);
                    v1 = expf(v1);
                    *(float2*)&g_eg[(size_t)m * C_DIM + cw] = make_float2(v0, v1);
                    float* dp = &g_denom[(size_t)grp * C_DIM + cw];
                    atomicAdd(dp,     v0);
                    atomicAdd(dp + 1, v1);
                } else {
                    float2 e = *(const float2*)&g_eg[(size_t)m * C_DIM + cw];
                    float2 d = *(const float2*)&g_denom[(size_t)grp * C_DIM + cw];
                    float* yp = &g_y[(size_t)grp * C_DIM + cw];
                    atomicAdd(yp,     v0 * (e.x / d.x));
                    atomicAdd(yp + 1, v1 * (e.y / d.y));
                }
            }
        }
    }
}

// ---------------- yh = y @ Wh + bh (fp32 SIMT, small) ----------------
__global__ __launch_bounds__(256, 2)
void gemm_h_kernel(const float* __restrict__ Wh, const float* __restrict__ bh)
{
    constexpr int BM = 128, BN = 128, BK = 16;
    __shared__ float As[BK][BM];
    __shared__ float Bs[BK][BN];

    const int tid  = threadIdx.x;
    const int col0 = blockIdx.x * BN;
    const int row0 = blockIdx.y * BM;
    const int ty = tid >> 4, tx = tid & 15;
    const int trow = ty * 8, tcol = tx * 8;

    float acc[8][8];
#pragma unroll
    for (int i = 0; i < 8; i++)
#pragma unroll
        for (int j = 0; j < 8; j++) acc[i][j] = 0.f;

    for (int k0 = 0; k0 < C_DIM; k0 += BK) {
#pragma unroll
        for (int s = 0; s < 2; s++) {
            int ll = tid + s * 256;
            int ar  = ll >> 2;
            int akq = (ll & 3) * 4;
            float4 av = *(const float4*)&g_y[(size_t)(row0 + ar) * C_DIM + k0 + akq];
            As[akq + 0][ar] = av.x;
            As[akq + 1][ar] = av.y;
            As[akq + 2][ar] = av.z;
            As[akq + 3][ar] = av.w;
            int bk  = ll >> 5;
            int bcq = (ll & 31) * 4;
            float4 bv = *(const float4*)&Wh[(size_t)(k0 + bk) * C_DIM + col0 + bcq];
            *(float4*)&Bs[bk][bcq] = bv;
        }
        __syncthreads();
#pragma unroll
        for (int k = 0; k < BK; k++) {
            float a[8], b[8];
#pragma unroll
            for (int i = 0; i < 8; i++) a[i] = As[k][trow + i];
#pragma unroll
            for (int j = 0; j < 8; j++) b[j] = Bs[k][tcol + j];
#pragma unroll
            for (int i = 0; i < 8; i++)
#pragma unroll
                for (int j = 0; j < 8; j++)
                    acc[i][j] = fmaf(a[i], b[j], acc[i][j]);
        }
        __syncthreads();
    }

    float bv[8];
#pragma unroll
    for (int j = 0; j < 8; j++) bv[j] = bh[col0 + tcol + j];
#pragma unroll
    for (int i = 0; i < 8; i++) {
        size_t off = (size_t)(row0 + trow + i) * C_DIM + col0 + tcol;
        *(float4*)&g_yh[off]     = make_float4(acc[i][0] + bv[0], acc[i][1] + bv[1],
                                               acc[i][2] + bv[2], acc[i][3] + bv[3]);
        *(float4*)&g_yh[off + 4] = make_float4(acc[i][4] + bv[4], acc[i][5] + bv[5],
                                               acc[i][6] + bv[6], acc[i][7] + bv[7]);
    }
}

// ---------------- out[n] = yh[ix[n]] ----------------
__global__ void gather_kernel(const int* __restrict__ ix, float* __restrict__ out) {
    size_t idx = (size_t)blockIdx.x * blockDim.x + threadIdx.x;  // N*C/4
    int n  = (int)(idx >> 7);
    int cq = (int)(idx & 127) << 2;
    int g  = ix[n];
    *(float4*)&out[((size_t)n << 9) + cq] = *(const float4*)&g_yh[((size_t)g << 9) + cq];
}

extern "C" void kernel_launch(void* const* d_in, const int* in_sizes, int n_in,
                              void* d_out, int out_size) {
    const float* x  = (const float*)d_in[0];
    const int*   ix = (const int*)d_in[1];
    const float* Wf = (const float*)d_in[2];
    const float* bf = (const float*)d_in[3];
    const float* Wg = (const float*)d_in[4];
    const float* bg = (const float*)d_in[5];
    const float* Wh = (const float*)d_in[6];
    const float* bh = (const float*)d_in[7];
    float* out = (float*)d_out;

    const int SMEM = 2 * 4 * TILE_E * 2;   // 81920 bytes
    cudaFuncSetAttribute(gemm_half<true>,  cudaFuncAttributeMaxDynamicSharedMemorySize, SMEM);
    cudaFuncSetAttribute(gemm_half<false>, cudaFuncAttributeMaxDynamicSharedMemorySize, SMEM);

    zero_kernel<<<(G_DIM * C_DIM / 4) / 256, 256>>>();
    build_w_kernel<<<(NOUT * C_DIM) / 256, 256>>>(Wf, Wg);

    dim3 g1(4, N_ELEM / 128);
    gemm_half<true><<<g1, 256, SMEM>>>(x, ix, bg);    // eg + denom
    gemm_half<false><<<g1, 256, SMEM>>>(x, ix, bf);   // fx, fused aggregation

    dim3 g2(C_DIM / 128, G_DIM / 128);
    gemm_h_kernel<<<g2, 256>>>(Wh, bh);

    gather_kernel<<<(N_ELEM * (C_DIM / 4)) / 256, 256>>>(ix, out);
}

// round 11
// speedup vs baseline: 1.0631x; 1.0144x over previous
#include <cuda_runtime.h>
#include <cuda_bf16.h>
#include <cuda_fp16.h>
#include <math.h>
#include <stdint.h>

#define N_ELEM 131072
#define C_DIM  512
#define G_DIM  4096
#define NOUT   1024     // Wf cols || Wg cols

// ---------------- scratch (device globals; no allocation allowed) ----------------
__device__ __nv_bfloat16 g_whi[(size_t)NOUT * C_DIM];     // 1 MB, K-major [n][k]
__device__ __nv_bfloat16 g_wlo[(size_t)NOUT * C_DIM];     // 1 MB
__device__ __half g_eg[(size_t)N_ELEM * C_DIM];           // 128 MB (fp16)
__device__ float g_denom[G_DIM * C_DIM];                  // 8 MB (then reciprocal)
__device__ float g_y[G_DIM * C_DIM];                      // 8 MB
__device__ float g_yh[G_DIM * C_DIM];                     // 8 MB

#define MMA16816(d, a0, a1, a2, a3, b0, b1) \
    asm volatile("mma.sync.aligned.m16n8k16.row.col.f32.bf16.bf16.f32 " \
                 "{%0,%1,%2,%3}, {%4,%5,%6,%7}, {%8,%9}, {%0,%1,%2,%3};" \
                 : "+f"((d)[0]), "+f"((d)[1]), "+f"((d)[2]), "+f"((d)[3]) \
                 : "r"(a0), "r"(a1), "r"(a2), "r"(a3), "r"(b0), "r"(b1))

__device__ __forceinline__ uint32_t smem_u32(const void* p) {
    uint32_t a;
    asm("{ .reg .u64 t; cvta.to.shared.u64 t, %1; cvt.u32.u64 %0, t; }" : "=r"(a) : "l"(p));
    return a;
}
__device__ __forceinline__ void cp16(uint32_t saddr, const void* g) {
    asm volatile("cp.async.cg.shared.global [%0], [%1], 16;" :: "r"(saddr), "l"(g));
}

// ---------------- zero accumulators ----------------
__global__ void zero_kernel() {
    int i = blockIdx.x * blockDim.x + threadIdx.x;   // G*C/4
    float4 z = make_float4(0.f, 0.f, 0.f, 0.f);
    ((float4*)g_denom)[i] = z;
    ((float4*)g_y)[i] = z;
}

// ---------------- denom -> 1/denom (between the two gemm halves) ----------------
__global__ void rcp_kernel() {
    int i = blockIdx.x * blockDim.x + threadIdx.x;   // G*C/4
    float4 d = ((float4*)g_denom)[i];
    d.x = 1.0f / d.x;
    d.y = 1.0f / d.y;
    d.z = 1.0f / d.z;
    d.w = 1.0f / d.w;
    ((float4*)g_denom)[i] = d;
}

// ---------------- build Whi/Wlo [n=1024][k=512] K-major bf16 ----------------
__global__ void build_w_kernel(const float* __restrict__ Wf,
                               const float* __restrict__ Wg) {
    int i = blockIdx.x * blockDim.x + threadIdx.x;   // NOUT*C_DIM
    int n = i >> 9;
    int k = i & 511;
    const float* W = (n < 512) ? Wf : Wg;
    float w = W[(size_t)k * C_DIM + (n & 511)];
    __nv_bfloat16 hi = __float2bfloat16(w);
    g_whi[i] = hi;
    g_wlo[i] = __float2bfloat16(w - __bfloat162float(hi));
}

// ---------------- mma.sync bf16-split GEMM halves ------------------------------
// Mainloop byte-identical to the 1425us best (R10). Epilogues updated:
// IS_G=true : eg = __expf(x Wg + bg) -> fp16 store; denom += quantized eg (fp32 atomics).
// IS_G=false: fx in regs -> w = eg_fp16 * rcp_denom, atomicAdd y += fx*w.
#define SPITCH 40
#define TILE_E (128 * SPITCH)        // bf16 elems per tile (10240 B)
#define STG_E  (4 * TILE_E)          // elems per stage (4 tiles)

template <bool IS_G>
__global__ __launch_bounds__(256, 2)
void gemm_half(const float* __restrict__ x, const int* __restrict__ ix,
               const float* __restrict__ bias) {
    extern __shared__ __nv_bfloat16 sm[];
    // stage s: [AHI, ALO, BHI, BLO], each 128 x SPITCH

    const int tid  = threadIdx.x;
    const int l    = tid & 31;
    const int warp = tid >> 5;
    const int bx   = blockIdx.x;          // 0..3 -> 128-col stripe of this half
    const int row0 = blockIdx.y * 128;
    const int n0g  = (IS_G ? 512 : 0) + bx * 128;

    const int wm = warp >> 2;             // 0..1
    const int wn = warp & 3;              // 0..3
    const int m_base = wm * 64;
    const int n_base = wn * 32;
    const int gid = l >> 2, tig = l & 3;

    float acc[4][4][4];
#pragma unroll
    for (int t = 0; t < 4; t++)
#pragma unroll
        for (int n = 0; n < 4; n++)
#pragma unroll
            for (int r = 0; r < 4; r++) acc[t][n][r] = 0.f;

    float4 stg[4];

#define LOAD_A(CH) do {                                                       \
        const int kc_ = (CH) * 32;                                            \
        _Pragma("unroll")                                                     \
        for (int i_ = 0; i_ < 4; i_++) {                                      \
            int u_ = tid + i_ * 256;                                          \
            int r_ = u_ >> 3, s_ = u_ & 7;                                    \
            stg[i_] = *(const float4*)(x + (size_t)(row0 + r_) * C_DIM + kc_ + s_ * 4); \
        }                                                                     \
    } while (0)

#define STORE_A(BUF) do {                                                     \
        __nv_bfloat16* ahi_ = sm + (BUF) * STG_E;                             \
        __nv_bfloat16* alo_ = ahi_ + TILE_E;                                  \
        _Pragma("unroll")                                                     \
        for (int i_ = 0; i_ < 4; i_++) {                                      \
            int u_ = tid + i_ * 256;                                          \
            int r_ = u_ >> 3, s_ = u_ & 7;                                    \
            float4 v_ = stg[i_];                                              \
            __nv_bfloat162 h01_, h23_, l01_, l23_;                            \
            h01_.x = __float2bfloat16(v_.x); h01_.y = __float2bfloat16(v_.y); \
            h23_.x = __float2bfloat16(v_.z); h23_.y = __float2bfloat16(v_.w); \
            l01_.x = __float2bfloat16(v_.x - __bfloat162float(h01_.x));       \
            l01_.y = __float2bfloat16(v_.y - __bfloat162float(h01_.y));       \
            l23_.x = __float2bfloat16(v_.z - __bfloat162float(h23_.x));       \
            l23_.y = __float2bfloat16(v_.w - __bfloat162float(h23_.y));       \
            uint2 H_, L_;                                                     \
            H_.x = *(uint32_t*)&h01_; H_.y = *(uint32_t*)&h23_;               \
            L_.x = *(uint32_t*)&l01_; L_.y = *(uint32_t*)&l23_;               \
            *(uint2*)(ahi_ + r_ * SPITCH + s_ * 4) = H_;                      \
            *(uint2*)(alo_ + r_ * SPITCH + s_ * 4) = L_;                      \
        }                                                                     \
    } while (0)

#define LOAD_B(BUF, CH) do {                                                  \
        const int kc_ = (CH) * 32;                                            \
        uint32_t bhi_ = smem_u32(sm + (BUF) * STG_E + 2 * TILE_E);            \
        uint32_t blo_ = bhi_ + TILE_E * 2;                                    \
        _Pragma("unroll")                                                     \
        for (int i_ = 0; i_ < 2; i_++) {                                      \
            int u_ = tid + i_ * 256;                                          \
            int nr_ = u_ >> 2, ch_ = u_ & 3;                                  \
            size_t go_ = (size_t)(n0g + nr_) * C_DIM + kc_ + ch_ * 8;         \
            uint32_t so_ = nr_ * (SPITCH * 2) + ch_ * 16;                     \
            cp16(bhi_ + so_, g_whi + go_);                                    \
            cp16(blo_ + so_, g_wlo + go_);                                    \
        }                                                                     \
        asm volatile("cp.async.commit_group;" ::: "memory");                  \
    } while (0)

    LOAD_B(0, 0);
    LOAD_A(0);
    STORE_A(0);
    asm volatile("cp.async.wait_group 0;" ::: "memory");
    __syncthreads();

    for (int it = 0; it < 16; it++) {
        const int cur = it & 1;
        if (it + 1 < 16) {
            LOAD_B(cur ^ 1, it + 1);
            LOAD_A(it + 1);
        }

        const __nv_bfloat16* Ahi = sm + cur * STG_E;
        const __nv_bfloat16* Alo = Ahi + TILE_E;
        const __nv_bfloat16* Bhi = Ahi + 2 * TILE_E;
        const __nv_bfloat16* Blo = Ahi + 3 * TILE_E;

#pragma unroll
        for (int s = 0; s < 2; s++) {
            const int k0 = s * 16 + 2 * tig;
            uint32_t bH[4][2], bL[4][2];
#pragma unroll
            for (int nt = 0; nt < 4; nt++) {
                const int rn = n_base + nt * 8 + gid;
                bH[nt][0] = *(const uint32_t*)(Bhi + rn * SPITCH + k0);
                bH[nt][1] = *(const uint32_t*)(Bhi + rn * SPITCH + k0 + 8);
                bL[nt][0] = *(const uint32_t*)(Blo + rn * SPITCH + k0);
                bL[nt][1] = *(const uint32_t*)(Blo + rn * SPITCH + k0 + 8);
            }
#pragma unroll
            for (int t = 0; t < 4; t++) {
                const int r = m_base + t * 16 + gid;
                uint32_t aH[4], aL[4];
                aH[0] = *(const uint32_t*)(Ahi + r * SPITCH + k0);
                aH[1] = *(const uint32_t*)(Ahi + (r + 8) * SPITCH + k0);
                aH[2] = *(const uint32_t*)(Ahi + r * SPITCH + k0 + 8);
                aH[3] = *(const uint32_t*)(Ahi + (r + 8) * SPITCH + k0 + 8);
                aL[0] = *(const uint32_t*)(Alo + r * SPITCH + k0);
                aL[1] = *(const uint32_t*)(Alo + (r + 8) * SPITCH + k0);
                aL[2] = *(const uint32_t*)(Alo + r * SPITCH + k0 + 8);
                aL[3] = *(const uint32_t*)(Alo + (r + 8) * SPITCH + k0 + 8);
                // pass-major: acc[t][nt] reuse distance = 4 independent MMAs
#pragma unroll
                for (int nt = 0; nt < 4; nt++)
                    MMA16816(acc[t][nt], aH[0], aH[1], aH[2], aH[3],
                             bH[nt][0], bH[nt][1]);
#pragma unroll
                for (int nt = 0; nt < 4; nt++)
                    MMA16816(acc[t][nt], aH[0], aH[1], aH[2], aH[3],
                             bL[nt][0], bL[nt][1]);
#pragma unroll
                for (int nt = 0; nt < 4; nt++)
                    MMA16816(acc[t][nt], aL[0], aL[1], aL[2], aL[3],
                             bH[nt][0], bH[nt][1]);
            }
        }

        if (it + 1 < 16) {
            STORE_A(cur ^ 1);
            asm volatile("cp.async.wait_group 0;" ::: "memory");
        }
        __syncthreads();
    }
#undef LOAD_A
#undef STORE_A
#undef LOAD_B

    // ---- epilogue ----
#pragma unroll
    for (int t = 0; t < 4; t++) {
#pragma unroll
        for (int h = 0; h < 2; h++) {
            const int m = row0 + m_base + t * 16 + gid + h * 8;
            const int grp = ix[m];
#pragma unroll
            for (int nt = 0; nt < 4; nt++) {
                const int cg = n0g + n_base + nt * 8 + 2 * tig;
                const int cw = cg & 511;
                float v0 = acc[t][nt][2 * h]     + bias[cw];
                float v1 = acc[t][nt][2 * h + 1] + bias[cw + 1];
                if (IS_G) {
                    v0 = __expf(v0);
                    v1 = __expf(v1);
                    // quantize to fp16, use quantized values for denom too
                    __half2 eq = __floats2half2_rn(v0, v1);
                    *(__half2*)&g_eg[(size_t)m * C_DIM + cw] = eq;
                    float q0 = __half2float(__low2half(eq));
                    float q1 = __half2float(__high2half(eq));
                    float* dp = &g_denom[(size_t)grp * C_DIM + cw];
                    atomicAdd(dp,     q0);
                    atomicAdd(dp + 1, q1);
                } else {
                    __half2 eh = *(const __half2*)&g_eg[(size_t)m * C_DIM + cw];
                    float2 e = __half22float2(eh);
                    float2 d = *(const float2*)&g_denom[(size_t)grp * C_DIM + cw]; // reciprocal
                    float* yp = &g_y[(size_t)grp * C_DIM + cw];
                    atomicAdd(yp,     v0 * e.x * d.x);
                    atomicAdd(yp + 1, v1 * e.y * d.y);
                }
            }
        }
    }
}

// ---------------- yh = y @ Wh + bh (fp32 SIMT, small) ----------------
__global__ __launch_bounds__(256, 2)
void gemm_h_kernel(const float* __restrict__ Wh, const float* __restrict__ bh)
{
    constexpr int BM = 128, BN = 128, BK = 16;
    __shared__ float As[BK][BM];
    __shared__ float Bs[BK][BN];

    const int tid  = threadIdx.x;
    const int col0 = blockIdx.x * BN;
    const int row0 = blockIdx.y * BM;
    const int ty = tid >> 4, tx = tid & 15;
    const int trow = ty * 8, tcol = tx * 8;

    float acc[8][8];
#pragma unroll
    for (int i = 0; i < 8; i++)
#pragma unroll
        for (int j = 0; j < 8; j++) acc[i][j] = 0.f;

    for (int k0 = 0; k0 < C_DIM; k0 += BK) {
#pragma unroll
        for (int s = 0; s < 2; s++) {
            int ll = tid + s * 256;
            int ar  = ll >> 2;
            int akq = (ll & 3) * 4;
            float4 av = *(const float4*)&g_y[(size_t)(row0 + ar) * C_DIM + k0 + akq];
            As[akq + 0][ar] = av.x;
            As[akq + 1][ar] = av.y;
            As[akq + 2][ar] = av.z;
            As[akq + 3][ar] = av.w;
            int bk  = ll >> 5;
            int bcq = (ll & 31) * 4;
            float4 bv = *(const float4*)&Wh[(size_t)(k0 + bk) * C_DIM + col0 + bcq];
            *(float4*)&Bs[bk][bcq] = bv;
        }
        __syncthreads();
#pragma unroll
        for (int k = 0; k < BK; k++) {
            float a[8], b[8];
#pragma unroll
            for (int i = 0; i < 8; i++) a[i] = As[k][trow + i];
#pragma unroll
            for (int j = 0; j < 8; j++) b[j] = Bs[k][tcol + j];
#pragma unroll
            for (int i = 0; i < 8; i++)
#pragma unroll
                for (int j = 0; j < 8; j++)
                    acc[i][j] = fmaf(a[i], b[j], acc[i][j]);
        }
        __syncthreads();
    }

    float bv[8];
#pragma unroll
    for (int j = 0; j < 8; j++) bv[j] = bh[col0 + tcol + j];
#pragma unroll
    for (int i = 0; i < 8; i++) {
        size_t off = (size_t)(row0 + trow + i) * C_DIM + col0 + tcol;
        *(float4*)&g_yh[off]     = make_float4(acc[i][0] + bv[0], acc[i][1] + bv[1],
                                               acc[i][2] + bv[2], acc[i][3] + bv[3]);
        *(float4*)&g_yh[off + 4] = make_float4(acc[i][4] + bv[4], acc[i][5] + bv[5],
                                               acc[i][6] + bv[6], acc[i][7] + bv[7]);
    }
}

// ---------------- out[n] = yh[ix[n]] ----------------
__global__ void gather_kernel(const int* __restrict__ ix, float* __restrict__ out) {
    size_t idx = (size_t)blockIdx.x * blockDim.x + threadIdx.x;  // N*C/4
    int n  = (int)(idx >> 7);
    int cq = (int)(idx & 127) << 2;
    int g  = ix[n];
    *(float4*)&out[((size_t)n << 9) + cq] = *(const float4*)&g_yh[((size_t)g << 9) + cq];
}

extern "C" void kernel_launch(void* const* d_in, const int* in_sizes, int n_in,
                              void* d_out, int out_size) {
    const float* x  = (const float*)d_in[0];
    const int*   ix = (const int*)d_in[1];
    const float* Wf = (const float*)d_in[2];
    const float* bf = (const float*)d_in[3];
    const float* Wg = (const float*)d_in[4];
    const float* bg = (const float*)d_in[5];
    const float* Wh = (const float*)d_in[6];
    const float* bh = (const float*)d_in[7];
    float* out = (float*)d_out;

    const int SMEM = 2 * 4 * TILE_E * 2;   // 81920 bytes
    cudaFuncSetAttribute(gemm_half<true>,  cudaFuncAttributeMaxDynamicSharedMemorySize, SMEM);
    cudaFuncSetAttribute(gemm_half<false>, cudaFuncAttributeMaxDynamicSharedMemorySize, SMEM);

    zero_kernel<<<(G_DIM * C_DIM / 4) / 256, 256>>>();
    build_w_kernel<<<(NOUT * C_DIM) / 256, 256>>>(Wf, Wg);

    dim3 g1(4, N_ELEM / 128);
    gemm_half<true><<<g1, 256, SMEM>>>(x, ix, bg);    // eg(fp16) + denom
    rcp_kernel<<<(G_DIM * C_DIM / 4) / 256, 256>>>(); // denom -> 1/denom
    gemm_half<false><<<g1, 256, SMEM>>>(x, ix, bf);   // fx, fused aggregation

    dim3 g2(C_DIM / 128, G_DIM / 128);
    gemm_h_kernel<<<g2, 256>>>(Wh, bh);

    gather_kernel<<<(N_ELEM * (C_DIM / 4)) / 256, 256>>>(ix, out);
}